// round 16
// baseline (speedup 1.0000x reference)
#include <cuda_runtime.h>
#include <cuda_fp16.h>
#include <math.h>
#include <stdint.h>

typedef __half h16;

#define NN 4096
#define EE 4096
#define FF 512
#define HD 512
#define NH 8
#define NL 4
#define NC 16
#define LNEPS 1e-5f
#define CAP 128
#define QKVW 1536

// ---------------- scratch ----------------
__device__ float g_Y[(size_t)EE * HD];
__device__ int   g_elist[(size_t)EE * CAP];
__device__ int   g_ecnt[EE];
__device__ int   g_nlist[(size_t)NN * CAP];
__device__ int   g_ncnt[NN];
__device__ float g_Xa[NN * HD];  __device__ h16 g_Xah[NN * HD];
__device__ float g_Xb[NN * HD];  __device__ h16 g_Xbh[NN * HD];
__device__ h16   g_X0h[NN * FF];
__device__ h16   g_QKV[(size_t)NN * QKVW];      // [Q|K|V] fp16
__device__ h16   g_VTh[(size_t)HD * NN];
__device__ float g_GV[NN * HD];
__device__ h16   g_CTXh[NN * HD];
__device__ float g_T[NN * HD];
__device__ float g_dv2[NN];
__device__ float g_invDE[EE];
__device__ h16   g_WTh[17 * HD * HD];
__device__ float g_bqkv[NL * QKVW];

// ---------------- helpers ----------------
__device__ __forceinline__ uint32_t smem_u32(const void* p) {
    uint32_t a;
    asm("{ .reg .u64 t; cvta.to.shared.u64 t, %1; cvt.u32.u64 %0, t; }" : "=r"(a) : "l"(p));
    return a;
}
__device__ __forceinline__ void cpa16(uint32_t dst, const void* src) {
    asm volatile("cp.async.cg.shared.global [%0], [%1], 16;\n" :: "r"(dst), "l"(src));
}
__device__ __forceinline__ void mma16816(float* c, const uint32_t* a, const uint32_t* b) {
    asm volatile(
        "mma.sync.aligned.m16n8k16.row.col.f32.f16.f16.f32 "
        "{%0,%1,%2,%3}, {%4,%5,%6,%7}, {%8,%9}, {%0,%1,%2,%3};\n"
        : "+f"(c[0]), "+f"(c[1]), "+f"(c[2]), "+f"(c[3])
        : "r"(a[0]), "r"(a[1]), "r"(a[2]), "r"(a[3]), "r"(b[0]), "r"(b[1]));
}
__device__ __forceinline__ uint32_t pk2(h16 a, h16 b) {
    union { __half2 v; uint32_t u; } cv;
    cv.v = __halves2half2(a, b);
    return cv.u;
}
__device__ __forceinline__ h16 toh(float v) { return __float2half_rn(v); }
__device__ __forceinline__ uint32_t mul2c(uint32_t u, __half2 c) {
    union { __half2 v; uint32_t u; } a;
    a.u = u; a.v = __hmul2(a.v, c);
    return a.u;
}

// ---------------- fp16 HMMA GEMM ----------------
struct TG {
    const h16 *Ah, *Bh;
    float* C; h16* Ch;
    const float* bias; const float* resid;
    long long sA, sB, sC, sR;
    int lda, ldb, ldc, ldr;
    float alpha, rscale;
    int K;
};

__global__ __launch_bounds__(256, 1) void hgemm_k(TG p) {
    constexpr int NT = 128;
    constexpr int NT8 = NT / 16;
    constexpr int TA = 128 * 40;
    constexpr int TB = NT * 40;
    constexpr int STG = TA + TB;
    extern __shared__ h16 sm[];

    const int tid = threadIdx.x, lid = tid & 31, wid = tid >> 5;
    const int wm = wid & 3, wn = wid >> 2;
    const int g = lid >> 2, tg = lid & 3;
    const long long z = blockIdx.z;
    const h16* Ah = p.Ah + z * p.sA;
    const h16* Bh = p.Bh + z * p.sB;
    const int m0 = blockIdx.y * 128, n0 = blockIdx.x * NT;

    float acc[2][NT8][4];
    #pragma unroll
    for (int i = 0; i < 2; i++)
        #pragma unroll
        for (int j = 0; j < NT8; j++)
            #pragma unroll
            for (int q = 0; q < 4; q++) acc[i][j][q] = 0.f;

    const int nkt = p.K >> 5;

    auto issue = [&](int kt) {
        h16* st = sm + (kt & 1) * STG;
        uint32_t sb = smem_u32(st);
        const long long ko = (long long)kt * 32;
        for (int ch = tid; ch < 512; ch += 256) {
            int r = ch >> 2, c = ch & 3;
            cpa16(sb + (uint32_t)(r * 40 + c * 8) * 2,
                  Ah + (long long)(m0 + r) * p.lda + ko + c * 8);
        }
        for (int ch = tid; ch < NT * 4; ch += 256) {
            int r = ch >> 2, c = ch & 3;
            cpa16(sb + (uint32_t)(TA + r * 40 + c * 8) * 2,
                  Bh + (long long)(n0 + r) * p.ldb + ko + c * 8);
        }
        asm volatile("cp.async.commit_group;\n");
    };

    issue(0);
    for (int kt = 0; kt < nkt; kt++) {
        if (kt + 1 < nkt) {
            issue(kt + 1);
            asm volatile("cp.async.wait_group 1;\n");
        } else {
            asm volatile("cp.async.wait_group 0;\n");
        }
        __syncthreads();
        const h16* st  = sm + (kt & 1) * STG;
        const h16* sAh = st;
        const h16* sBh = st + TA;
        #pragma unroll
        for (int ks = 0; ks < 2; ks++) {
            uint32_t ah[2][4], bh[NT8][2];
            #pragma unroll
            for (int mi = 0; mi < 2; mi++) {
                int r0 = (wm * 32 + mi * 16 + g) * 40 + ks * 16 + 2 * tg;
                ah[mi][0] = *(const uint32_t*)(sAh + r0);
                ah[mi][1] = *(const uint32_t*)(sAh + r0 + 320);
                ah[mi][2] = *(const uint32_t*)(sAh + r0 + 8);
                ah[mi][3] = *(const uint32_t*)(sAh + r0 + 328);
            }
            #pragma unroll
            for (int ni = 0; ni < NT8; ni++) {
                int r0 = (wn * (NT / 2) + ni * 8 + g) * 40 + ks * 16 + 2 * tg;
                bh[ni][0] = *(const uint32_t*)(sBh + r0);
                bh[ni][1] = *(const uint32_t*)(sBh + r0 + 8);
            }
            #pragma unroll
            for (int mi = 0; mi < 2; mi++)
                #pragma unroll
                for (int ni = 0; ni < NT8; ni++)
                    mma16816(acc[mi][ni], ah[mi], bh[ni]);
        }
        __syncthreads();
    }

    float* Cp  = p.C  ? p.C  + z * p.sC : (float*)0;
    h16*   Chp = p.Ch ? p.Ch + z * p.sC : (h16*)0;
    const float* Rp = p.resid ? p.resid + z * p.sR : (const float*)0;

    #pragma unroll
    for (int mi = 0; mi < 2; mi++)
        #pragma unroll
        for (int ni = 0; ni < NT8; ni++) {
            const int n = n0 + wn * (NT / 2) + ni * 8 + 2 * tg;
            #pragma unroll
            for (int h = 0; h < 2; h++) {
                const int m = m0 + wm * 32 + mi * 16 + g + h * 8;
                float2 v = make_float2(acc[mi][ni][h * 2 + 0] * p.alpha,
                                       acc[mi][ni][h * 2 + 1] * p.alpha);
                if (p.bias) {
                    float2 bb = *(const float2*)(p.bias + n);
                    v.x += bb.x; v.y += bb.y;
                }
                if (Rp) {
                    float2 rr = *(const float2*)(Rp + (long long)m * p.ldr + n);
                    v.x += p.rscale * rr.x; v.y += p.rscale * rr.y;
                }
                if (Cp) *(float2*)(Cp + (long long)m * p.ldc + n) = v;
                if (Chp)
                    *(uint32_t*)(Chp + (long long)m * p.ldc + n) =
                        pk2(toh(v.x), toh(v.y));
            }
        }
}

// ---------------- fused flash attention (fp16, strided Q/K) ----------------
#define FVO  9216
#define FSTG 17920
#define FSMEM (2 * FSTG * 2)

__global__ __launch_bounds__(256) void flash_k(
    const h16* __restrict__ Qh, const h16* __restrict__ Kh, int ldq,
    const h16* __restrict__ VTh, const float* __restrict__ GV,
    h16* __restrict__ CTXh) {
    extern __shared__ h16 fsm[];
    const int tid = threadIdx.x, lid = tid & 31, wid = tid >> 5;
    const int g = lid >> 2, tg = lid & 3;
    const int h = blockIdx.y;
    const int m0 = blockIdx.x * 128;
    const int qrow = m0 + wid * 16 + g;

    uint32_t qf[4][4];
    const __half2 c125 = __float2half2_rn(0.125f);
    #pragma unroll
    for (int ks = 0; ks < 4; ks++) {
        int col = h * 64 + ks * 16 + 2 * tg;
        const h16* q0 = Qh + (size_t)qrow * ldq + col;
        qf[ks][0] = mul2c(*(const uint32_t*)q0, c125);
        qf[ks][1] = mul2c(*(const uint32_t*)(q0 + 8 * ldq), c125);
        qf[ks][2] = mul2c(*(const uint32_t*)(q0 + 8), c125);
        qf[ks][3] = mul2c(*(const uint32_t*)(q0 + 8 * ldq + 8), c125);
    }

    float m0s = -1e30f, m1s = -1e30f, l0 = 0.f, l1 = 0.f;
    float cO[8][4];
    #pragma unroll
    for (int i = 0; i < 8; i++)
        #pragma unroll
        for (int q = 0; q < 4; q++) cO[i][q] = 0.f;

    auto issue = [&](int j) {
        h16* st = fsm + (j & 1) * FSTG;
        uint32_t sb = smem_u32(st);
        const int kv0 = j * 128;
        for (int ch = tid; ch < 1024; ch += 256) {
            int r = ch >> 3, c = ch & 7;
            cpa16(sb + (uint32_t)(r * 72 + c * 8) * 2,
                  Kh + (size_t)(kv0 + r) * ldq + h * 64 + c * 8);
        }
        for (int ch = tid; ch < 1024; ch += 256) {
            int r = ch >> 4, c = ch & 15;
            cpa16(sb + (uint32_t)(FVO + r * 136 + c * 8) * 2,
                  VTh + (size_t)(h * 64 + r) * NN + kv0 + c * 8);
        }
        asm volatile("cp.async.commit_group;\n");
    };

    issue(0);
    for (int j = 0; j < 32; j++) {
        if (j + 1 < 32) {
            issue(j + 1);
            asm volatile("cp.async.wait_group 1;\n");
        } else {
            asm volatile("cp.async.wait_group 0;\n");
        }
        __syncthreads();
        const h16* st = fsm + (j & 1) * FSTG;
        const h16* sK = st;
        const h16* sV = st + FVO;

        float cS[16][4];
        #pragma unroll
        for (int i = 0; i < 16; i++)
            #pragma unroll
            for (int q = 0; q < 4; q++) cS[i][q] = 0.f;
        #pragma unroll
        for (int ks = 0; ks < 4; ks++) {
            #pragma unroll
            for (int ni = 0; ni < 16; ni++) {
                int off = (ni * 8 + g) * 72 + ks * 16 + 2 * tg;
                uint32_t bh[2] = {*(const uint32_t*)(sK + off),
                                  *(const uint32_t*)(sK + off + 8)};
                mma16816(cS[ni], qf[ks], bh);
            }
        }

        float mt0 = -1e30f, mt1 = -1e30f;
        #pragma unroll
        for (int ni = 0; ni < 16; ni++) {
            mt0 = fmaxf(mt0, fmaxf(cS[ni][0], cS[ni][1]));
            mt1 = fmaxf(mt1, fmaxf(cS[ni][2], cS[ni][3]));
        }
        mt0 = fmaxf(mt0, __shfl_xor_sync(0xffffffffu, mt0, 1));
        mt0 = fmaxf(mt0, __shfl_xor_sync(0xffffffffu, mt0, 2));
        mt1 = fmaxf(mt1, __shfl_xor_sync(0xffffffffu, mt1, 1));
        mt1 = fmaxf(mt1, __shfl_xor_sync(0xffffffffu, mt1, 2));
        float mn0 = fmaxf(m0s, mt0), mn1 = fmaxf(m1s, mt1);
        float sc0 = __expf(m0s - mn0), sc1 = __expf(m1s - mn1);
        l0 *= sc0; l1 *= sc1;
        #pragma unroll
        for (int nv = 0; nv < 8; nv++) {
            cO[nv][0] *= sc0; cO[nv][1] *= sc0;
            cO[nv][2] *= sc1; cO[nv][3] *= sc1;
        }
        m0s = mn0; m1s = mn1;

        #pragma unroll
        for (int ks = 0; ks < 8; ks++) {
            uint32_t pa[4];
            #pragma unroll
            for (int half = 0; half < 2; half++) {
                int ni = 2 * ks + half;
                float p0 = __expf(cS[ni][0] - mn0);
                float p1 = __expf(cS[ni][1] - mn0);
                float p2 = __expf(cS[ni][2] - mn1);
                float p3 = __expf(cS[ni][3] - mn1);
                l0 += p0 + p1; l1 += p2 + p3;
                pa[2 * half + 0] = pk2(toh(p0), toh(p1));
                pa[2 * half + 1] = pk2(toh(p2), toh(p3));
            }
            #pragma unroll
            for (int nv = 0; nv < 8; nv++) {
                int off = (nv * 8 + g) * 136 + ks * 16 + 2 * tg;
                uint32_t bh[2] = {*(const uint32_t*)(sV + off),
                                  *(const uint32_t*)(sV + off + 8)};
                mma16816(cO[nv], pa, bh);
            }
        }
        __syncthreads();
    }

    l0 += __shfl_xor_sync(0xffffffffu, l0, 1);
    l0 += __shfl_xor_sync(0xffffffffu, l0, 2);
    l1 += __shfl_xor_sync(0xffffffffu, l1, 1);
    l1 += __shfl_xor_sync(0xffffffffu, l1, 2);
    float i0 = 0.5f / l0, i1 = 0.5f / l1;
    #pragma unroll
    for (int nv = 0; nv < 8; nv++) {
        int col = h * 64 + nv * 8 + 2 * tg;
        size_t o0 = (size_t)qrow * HD + col;
        size_t o1 = o0 + 8 * HD;
        float2 g0 = *(const float2*)(GV + o0);
        float2 g1 = *(const float2*)(GV + o1);
        *(uint32_t*)(CTXh + o0) = pk2(toh(cO[nv][0] * i0 + g0.x),
                                      toh(cO[nv][1] * i0 + g0.y));
        *(uint32_t*)(CTXh + o1) = pk2(toh(cO[nv][2] * i1 + g1.x),
                                      toh(cO[nv][3] * i1 + g1.y));
    }
}

// ---------------- adjacency build + degrees ----------------
__global__ void zero_i_k(int* __restrict__ a, int n) {
    int i = blockIdx.x * 256 + threadIdx.x;
    if (i < n) a[i] = 0;
}
__global__ void build_k(const float* __restrict__ H,
                        int* __restrict__ elist, int* __restrict__ ecnt,
                        int* __restrict__ nlist, int* __restrict__ ncnt) {
    int i = blockIdx.x;
    for (int e4 = threadIdx.x; e4 < EE / 4; e4 += 256) {
        float4 v = *(const float4*)(H + (size_t)i * EE + 4 * e4);
        float vv[4] = {v.x, v.y, v.z, v.w};
        #pragma unroll
        for (int j = 0; j < 4; j++) {
            if (vv[j] != 0.f) {
                int e = 4 * e4 + j;
                int p = atomicAdd(&ecnt[e], 1);
                if (p < CAP) elist[(size_t)e * CAP + p] = i;
                int q = atomicAdd(&ncnt[i], 1);
                if (q < CAP) nlist[(size_t)i * CAP + q] = e;
            }
        }
    }
}
__global__ void deg_k(const int* __restrict__ ecnt, const int* __restrict__ ncnt,
                      float* __restrict__ invDE, float* __restrict__ dv2) {
    int i = blockIdx.x * 256 + threadIdx.x;
    if (i < EE) invDE[i] = 1.f / (float)ecnt[i];
    if (i < NN) dv2[i] = (i == 0) ? 1.f : rsqrtf((float)ncnt[i]);
}
// pack [bq|bk|bv] per layer into contiguous 1536-wide bias
__global__ void packb_k(const float* __restrict__ bq, const float* __restrict__ bk,
                        const float* __restrict__ bv, float* __restrict__ bqkv) {
    int i = blockIdx.x * 256 + threadIdx.x;       // NL*QKVW total
    int l = i / QKVW, c = i % QKVW;
    float v;
    if (c < HD)            v = bq[l * HD + c];
    else if (c < 2 * HD)   v = bk[l * HD + c - HD];
    else                   v = bv[l * HD + c - 2 * HD];
    bqkv[i] = v;
}
// Y[e,:] = invDE[e] * sum_{i in e} dv2[i] * V[i,:]   (V fp16, stride ldv)
__global__ __launch_bounds__(128) void spmm_edge_k(
    const int* __restrict__ elist, const int* __restrict__ ecnt,
    const float* __restrict__ dv2, const float* __restrict__ invDE,
    const h16* __restrict__ V, int ldv, float* __restrict__ Y) {
    int e = blockIdx.x, t = threadIdx.x;
    int cnt = ecnt[e]; if (cnt > CAP) cnt = CAP;
    const int* lst = elist + (size_t)e * CAP;
    float4 acc = make_float4(0.f, 0.f, 0.f, 0.f);
    for (int k = 0; k < cnt; k++) {
        int i = lst[k];
        float w = dv2[i];
        uint2 u = *(const uint2*)(V + (size_t)i * ldv + 4 * t);
        __half2 a, b;
        *(uint32_t*)&a = u.x; *(uint32_t*)&b = u.y;
        float2 fa = __half22float2(a), fb = __half22float2(b);
        acc.x += w * fa.x; acc.y += w * fa.y;
        acc.z += w * fb.x; acc.w += w * fb.y;
    }
    float s = invDE[e];
    acc.x *= s; acc.y *= s; acc.z *= s; acc.w *= s;
    *(float4*)(Y + (size_t)e * HD + 4 * t) = acc;
}
__global__ __launch_bounds__(128) void spmm_node_k(
    const int* __restrict__ nlist, const int* __restrict__ ncnt,
    const float* __restrict__ dv2, const float* __restrict__ Y,
    float* __restrict__ GV) {
    int i = blockIdx.x, t = threadIdx.x;
    int cnt = ncnt[i]; if (cnt > CAP) cnt = CAP;
    const int* lst = nlist + (size_t)i * CAP;
    float4 acc = make_float4(0.f, 0.f, 0.f, 0.f);
    for (int k = 0; k < cnt; k++) {
        int e = lst[k];
        float4 v = *(const float4*)(Y + (size_t)e * HD + 4 * t);
        acc.x += v.x; acc.y += v.y; acc.z += v.z; acc.w += v.w;
    }
    float s = 0.5f * dv2[i];
    acc.x *= s; acc.y *= s; acc.z *= s; acc.w *= s;
    *(float4*)(GV + (size_t)i * HD + 4 * t) = acc;
}

// ---------------- convert / transpose ----------------
__global__ void split_k(const float* __restrict__ in, h16* __restrict__ oh,
                        long long n) {
    long long i = (long long)blockIdx.x * 256 + threadIdx.x;
    if (i >= n) return;
    oh[i] = toh(in[i]);
}
__global__ void tsplit_k(const float* __restrict__ in, h16* __restrict__ oh,
                         int R, int C) {
    __shared__ float t[32][33];
    int c0 = blockIdx.x * 32, r0 = blockIdx.y * 32;
    int x = threadIdx.x, y = threadIdx.y;
    #pragma unroll
    for (int i = 0; i < 4; i++)
        t[y + i * 8][x] = in[(size_t)(r0 + y + i * 8) * C + c0 + x];
    __syncthreads();
    #pragma unroll
    for (int i = 0; i < 4; i++)
        oh[(size_t)(c0 + y + i * 8) * R + r0 + x] = toh(t[x][y + i * 8]);
}
// fp16-source transpose: in [R rows, stride ldin] -> out [cols][R]
__global__ void th_k(const h16* __restrict__ in, int ldin,
                     h16* __restrict__ oh, int R) {
    __shared__ h16 t[32][34];
    int c0 = blockIdx.x * 32, r0 = blockIdx.y * 32;
    int x = threadIdx.x, y = threadIdx.y;
    #pragma unroll
    for (int i = 0; i < 4; i++)
        t[y + i * 8][x] = in[(size_t)(r0 + y + i * 8) * ldin + c0 + x];
    __syncthreads();
    #pragma unroll
    for (int i = 0; i < 4; i++)
        oh[(size_t)(c0 + y + i * 8) * R + r0 + x] = t[x][y + i * 8];
}

// ---------------- LayerNorm + PReLU ----------------
__global__ void ln_prelu_k(const float* __restrict__ T, const float* __restrict__ g,
                           const float* __restrict__ b, const float* __restrict__ a_ptr,
                           float* __restrict__ out, h16* __restrict__ oh) {
    int row = blockIdx.x;
    const float* t = T + (size_t)row * HD;
    __shared__ float red[128];
    int tid = threadIdx.x;
    float v[4]; float s = 0.f;
    #pragma unroll
    for (int i = 0; i < 4; i++) { v[i] = t[tid + i * 128]; s += v[i]; }
    red[tid] = s; __syncthreads();
    for (int st = 64; st > 0; st >>= 1) {
        if (tid < st) red[tid] += red[tid + st];
        __syncthreads();
    }
    float mu = red[0] / HD; __syncthreads();
    float s2 = 0.f;
    #pragma unroll
    for (int i = 0; i < 4; i++) { float d = v[i] - mu; s2 += d * d; }
    red[tid] = s2; __syncthreads();
    for (int st = 64; st > 0; st >>= 1) {
        if (tid < st) red[tid] += red[tid + st];
        __syncthreads();
    }
    float inv = rsqrtf(red[0] / HD + LNEPS);
    float a = *a_ptr;
    #pragma unroll
    for (int i = 0; i < 4; i++) {
        int c = tid + i * 128;
        float o = (v[i] - mu) * inv * g[c] + b[c];
        o = (o >= 0.f) ? o : a * o;
        size_t idx = (size_t)row * HD + c;
        out[idx] = o;
        oh[idx] = toh(o);
    }
}

// ---------------- classifier + log-softmax ----------------
__global__ void cls_k(const float* __restrict__ X, const float* __restrict__ W,
                      const float* __restrict__ b, float* __restrict__ out) {
    int t = threadIdx.x;
    int r = blockIdx.x * 8 + (t >> 4);
    int c = t & 15;
    const float* x = X + (size_t)r * HD;
    float acc = 0.f;
    for (int k = 0; k < HD; k++) acc += x[k] * W[k * NC + c];
    out[(size_t)r * NC + c] = acc + b[c];
}
__global__ void logsoftmax_k(const float* __restrict__ L, float* __restrict__ out) {
    int row = blockIdx.x * 256 + threadIdx.x;
    if (row >= NN) return;
    const float* l = L + (size_t)row * NC;
    float mx = -1e30f;
    #pragma unroll
    for (int i = 0; i < NC; i++) mx = fmaxf(mx, l[i]);
    float s = 0.f;
    #pragma unroll
    for (int i = 0; i < NC; i++) s += __expf(l[i] - mx);
    float lse = mx + logf(s);
    #pragma unroll
    for (int i = 0; i < NC; i++) out[(size_t)row * NC + i] = l[i] - lse;
}

// ---------------- host ----------------
static void tg(const h16* Ah, int lda,
               const h16* Bh, int ldb,
               float* C, h16* Ch, int ldc,
               const float* bias, const float* resid, int ldr,
               float alpha, float rscale, int M, int N, int K) {
    TG p;
    p.Ah = Ah; p.Bh = Bh;
    p.C = C; p.Ch = Ch;
    p.bias = bias; p.resid = resid;
    p.sA = 0; p.sB = 0; p.sC = 0; p.sR = 0;
    p.lda = lda; p.ldb = ldb; p.ldc = ldc; p.ldr = ldr;
    p.alpha = alpha; p.rscale = rscale;
    p.K = K;
    dim3 grid(N / 128, M / 128, 1);
    const int smem = 2 * (128 * 40 + 128 * 40) * 2;
    cudaFuncSetAttribute(hgemm_k, cudaFuncAttributeMaxDynamicSharedMemorySize, smem);
    hgemm_k<<<grid, 256, smem>>>(p);
}

extern "C" void kernel_launch(void* const* d_in, const int* in_sizes, int n_in,
                              void* d_out, int out_size) {
    const float* X0      = (const float*)d_in[0];
    const float* H       = (const float*)d_in[1];
    const float* w_feat  = (const float*)d_in[2];
    const float* b_feat  = (const float*)d_in[3];
    const float* Wq      = (const float*)d_in[4];
    const float* bq      = (const float*)d_in[5];
    const float* Wk      = (const float*)d_in[6];
    const float* bk      = (const float*)d_in[7];
    const float* Wv      = (const float*)d_in[8];
    const float* bv      = (const float*)d_in[9];
    const float* Wo      = (const float*)d_in[10];
    const float* bo      = (const float*)d_in[11];
    const float* ln_g    = (const float*)d_in[12];
    const float* ln_b    = (const float*)d_in[13];
    const float* prelu_a = (const float*)d_in[14];
    const float* w_cls   = (const float*)d_in[15];
    const float* b_cls   = (const float*)d_in[16];
    float* out = (float*)d_out;

    float *Y, *Xa, *Xb, *GV, *T, *dv2, *invDE, *bqkv;
    int *elist, *ecnt, *nlist, *ncnt;
    h16 *Xah, *Xbh, *X0h, *QKV, *VTh, *CTXh, *WTh;
    cudaGetSymbolAddress((void**)&Y, g_Y);
    cudaGetSymbolAddress((void**)&elist, g_elist);
    cudaGetSymbolAddress((void**)&ecnt, g_ecnt);
    cudaGetSymbolAddress((void**)&nlist, g_nlist);
    cudaGetSymbolAddress((void**)&ncnt, g_ncnt);
    cudaGetSymbolAddress((void**)&Xa, g_Xa);
    cudaGetSymbolAddress((void**)&Xah, g_Xah);
    cudaGetSymbolAddress((void**)&Xb, g_Xb);
    cudaGetSymbolAddress((void**)&Xbh, g_Xbh);
    cudaGetSymbolAddress((void**)&X0h, g_X0h);
    cudaGetSymbolAddress((void**)&QKV, g_QKV);
    cudaGetSymbolAddress((void**)&VTh, g_VTh);
    cudaGetSymbolAddress((void**)&GV, g_GV);
    cudaGetSymbolAddress((void**)&CTXh, g_CTXh);
    cudaGetSymbolAddress((void**)&T, g_T);
    cudaGetSymbolAddress((void**)&dv2, g_dv2);
    cudaGetSymbolAddress((void**)&invDE, g_invDE);
    cudaGetSymbolAddress((void**)&WTh, g_WTh);
    cudaGetSymbolAddress((void**)&bqkv, g_bqkv);

    cudaFuncSetAttribute(flash_k, cudaFuncAttributeMaxDynamicSharedMemorySize, FSMEM);

    // adjacency + degrees
    zero_i_k<<<(EE + 255) / 256, 256>>>(ecnt, EE);
    zero_i_k<<<(NN + 255) / 256, 256>>>(ncnt, NN);
    build_k<<<NN, 256>>>(H, elist, ecnt, nlist, ncnt);
    deg_k<<<(NN + 255) / 256, 256>>>(ecnt, ncnt, invDE, dv2);
    packb_k<<<(NL * QKVW) / 256, 256>>>(bq, bk, bv, bqkv);

    // operand prep
    split_k<<<(NN * FF + 255) / 256, 256>>>(X0, X0h, (long long)NN * FF);
    dim3 tb(32, 8);
    tsplit_k<<<dim3(HD / 32, FF / 32), tb>>>(w_feat, WTh, FF, HD);
    for (int l = 0; l < NL; l++) {
        size_t w0 = (size_t)l * HD * HD;
        const float* ws[4] = {Wq + w0, Wk + w0, Wv + w0, Wo + w0};
        for (int j = 0; j < 4; j++) {
            size_t o = (1 + 4 * (size_t)l + j) * HD * HD;
            tsplit_k<<<dim3(HD / 32, HD / 32), tb>>>(ws[j], WTh + o, HD, HD);
        }
    }

    // input projection
    tg(X0h, FF, WTh, FF, Xa, Xah, HD, b_feat, 0, 0, 1.f, 0.f, NN, HD, FF);

    float* xf = Xa; h16* xh = Xah;
    float* yf = Xb; h16* yh = Xbh;
    for (int l = 0; l < NL; l++) {
        size_t wq_ = (1 + 4 * (size_t)l + 0) * HD * HD;   // Wq|Wk|Wv contiguous
        size_t wo_ = (1 + 4 * (size_t)l + 3) * HD * HD;

        // fused QKV: one GEMM, N=1536, contiguous output
        tg(xh, HD, WTh + wq_, HD, 0, QKV, QKVW,
           bqkv + (size_t)l * QKVW, 0, 0, 1.f, 0.f, NN, QKVW, HD);

        const h16* Qp = QKV;
        const h16* Kp = QKV + HD;
        const h16* Vp = QKV + 2 * HD;

        // V^T fp16 (strided fp16 source)
        th_k<<<dim3(HD / 32, NN / 32), tb>>>(Vp, QKVW, VTh, NN);

        // sparse GV from fp16 V
        spmm_edge_k<<<EE, 128>>>(elist, ecnt, dv2, invDE, Vp, QKVW, Y);
        spmm_node_k<<<NN, 128>>>(nlist, ncnt, dv2, Y, GV);

        // fused attention
        flash_k<<<dim3(NN / 128, NH), 256, FSMEM>>>(Qp, Kp, QKVW, VTh, GV, CTXh);

        // T = CTX @ Wo + bo + x
        tg(CTXh, HD, WTh + wo_, HD, T, 0, HD,
           bo + (size_t)l * HD, xf, HD, 1.f, 1.f, NN, HD, HD);

        ln_prelu_k<<<NN, 128>>>(T, ln_g + (size_t)l * HD, ln_b + (size_t)l * HD,
                                prelu_a + l, yf, yh);

        float* tf = xf; xf = yf; yf = tf;
        h16* th = xh; xh = yh; yh = th;
    }

    cls_k<<<NN / 8, 128>>>(xf, w_cls, b_cls, T);
    logsoftmax_k<<<NN / 256, 256>>>(T, out);
}